// round 2
// baseline (speedup 1.0000x reference)
#include <cuda_runtime.h>
#include <math.h>

#define MAXN   8192
#define TILE   128
#define KC     32
#define MAXT   (MAXN / TILE)                       // 64
#define MAXNB  (MAXT * (MAXT + 1) / 2)             // 2080

// Scratch (device globals: allocation-free)
__device__ float g_xn[MAXN * 128];                 // normalized, label-grouped rows
__device__ int   g_src[MAXN];                      // g_xn[r] = normalize(emb[g_src[r]])
__device__ int   g_c0;                             // count of label==0
__device__ float g_part[MAXNB * 2];                // per-block partial sums (class0, class1)

// ---------------------------------------------------------------------------
// Kernel 1: deterministic stable grouping permutation (single block scan)
// ---------------------------------------------------------------------------
__global__ void group_kernel(const int* __restrict__ label, int N) {
    __shared__ int sh[1024];
    const int t  = threadIdx.x;
    const int NT = blockDim.x;                     // 1024
    const int chunk = (N + NT - 1) / NT;
    const int s = min(t * chunk, N);
    const int e = min(s + chunk, N);

    int c0 = 0;
    for (int i = s; i < e; i++) c0 += (label[i] == 0);
    sh[t] = c0;
    __syncthreads();

    // Hillis-Steele inclusive scan over 1024 counts
    for (int off = 1; off < NT; off <<= 1) {
        int v = (t >= off) ? sh[t - off] : 0;
        __syncthreads();
        sh[t] += v;
        __syncthreads();
    }
    const int incl = sh[t];
    const int C0   = sh[NT - 1];
    if (t == 0) g_c0 = C0;

    int p0 = incl - c0;                            // zeros before my chunk
    int p1 = s - p0;                               // ones before my chunk
    for (int i = s; i < e; i++) {
        if (label[i] == 0) g_src[p0++] = i;
        else               g_src[C0 + p1++] = i;
    }
}

// ---------------------------------------------------------------------------
// Kernel 2: normalize rows + gather into grouped order (1 warp / row)
// ---------------------------------------------------------------------------
__global__ void norm_kernel(const float* __restrict__ emb, int N) {
    const int r = blockIdx.x * 8 + (threadIdx.x >> 5);
    const int lane = threadIdx.x & 31;
    if (r >= N) return;
    const int src = g_src[r];
    float4 v = ((const float4*)(emb + (size_t)src * 128))[lane];
    float ss = v.x * v.x + v.y * v.y + v.z * v.z + v.w * v.w;
    #pragma unroll
    for (int o = 16; o; o >>= 1) ss += __shfl_xor_sync(0xffffffffu, ss, o);
    const float scale = 1.0f / fmaxf(sqrtf(ss), 1e-12f);
    v.x *= scale; v.y *= scale; v.z *= scale; v.w *= scale;
    ((float4*)(g_xn + (size_t)r * 128))[lane] = v;
}

// ---------------------------------------------------------------------------
// Kernel 3: triangular 128x128 tile GEMM + exp/mask epilogue
//   - only upper-triangle tile pairs (bj >= bi); unordered pairs weighted x2 later
//   - skip tiles whose i-range is fully class0 and j-range fully class1
// ---------------------------------------------------------------------------
__global__ __launch_bounds__(256, 2) void tile_kernel(int N, int T) {
    // closed-form triangular decode: blockIdx.x -> (bi, bj), bj >= bi
    const int b = blockIdx.x;
    const float Tf = (float)T;
    int bi = (int)(Tf + 0.5f - sqrtf((Tf + 0.5f) * (Tf + 0.5f) - 2.0f * (float)b));
    // correct any fp rounding
    while (bi > 0 && b < bi * T - bi * (bi - 1) / 2) bi--;
    while (b >= (bi + 1) * T - bi * (bi + 1) / 2) bi++;
    const int bj = bi + (b - (bi * T - bi * (bi - 1) / 2));
    const int rb = bi * TILE, cb = bj * TILE;
    const int C0 = g_c0;
    const int outIdx = blockIdx.x * 2;
    const int tid = threadIdx.x;

    if (rb + TILE <= C0 && cb >= C0) {             // fully cross-class: no pairs
        if (tid == 0) { g_part[outIdx] = 0.0f; g_part[outIdx + 1] = 0.0f; }
        return;
    }

    __shared__ __align__(16) float As[KC][TILE + 4];
    __shared__ __align__(16) float Bs[KC][TILE + 4];
    __shared__ float red[256];

    float acc[8][8];
    #pragma unroll
    for (int i = 0; i < 8; i++)
        #pragma unroll
        for (int j = 0; j < 8; j++) acc[i][j] = 0.0f;

    const int tx = tid & 15, ty = tid >> 4;        // 16x16 thread grid, 8x8 micro-tile
    const int lr = tid >> 3;                       // 0..31 (row within pass)
    const int lk = (tid & 7) * 4;                  // 0,4,...,28 (k offset)

    for (int k0 = 0; k0 < 128; k0 += KC) {
        __syncthreads();
        #pragma unroll
        for (int rr = 0; rr < TILE; rr += 32) {
            const int row = rb + lr + rr;
            float4 a = (row < N) ? *(const float4*)(g_xn + (size_t)row * 128 + k0 + lk)
                                 : make_float4(0.f, 0.f, 0.f, 0.f);
            As[lk + 0][lr + rr] = a.x; As[lk + 1][lr + rr] = a.y;
            As[lk + 2][lr + rr] = a.z; As[lk + 3][lr + rr] = a.w;

            const int col = cb + lr + rr;
            float4 bb = (col < N) ? *(const float4*)(g_xn + (size_t)col * 128 + k0 + lk)
                                  : make_float4(0.f, 0.f, 0.f, 0.f);
            Bs[lk + 0][lr + rr] = bb.x; Bs[lk + 1][lr + rr] = bb.y;
            Bs[lk + 2][lr + rr] = bb.z; Bs[lk + 3][lr + rr] = bb.w;
        }
        __syncthreads();

        #pragma unroll
        for (int k = 0; k < KC; k++) {
            float4 a0 = *(const float4*)&As[k][ty * 8];
            float4 a1 = *(const float4*)&As[k][ty * 8 + 4];
            float4 b0 = *(const float4*)&Bs[k][tx * 8];
            float4 b1 = *(const float4*)&Bs[k][tx * 8 + 4];
            const float av[8] = {a0.x, a0.y, a0.z, a0.w, a1.x, a1.y, a1.z, a1.w};
            const float bv[8] = {b0.x, b0.y, b0.z, b0.w, b1.x, b1.y, b1.z, b1.w};
            #pragma unroll
            for (int i = 0; i < 8; i++)
                #pragma unroll
                for (int j = 0; j < 8; j++)
                    acc[i][j] = fmaf(av[i], bv[j], acc[i][j]);
        }
    }

    // epilogue: exp + label mask + strict upper triangle (i < j)
    float s0 = 0.0f, s1 = 0.0f;
    const int gi0 = rb + ty * 8, gj0 = cb + tx * 8;
    #pragma unroll
    for (int i = 0; i < 8; i++) {
        const int gi = gi0 + i;
        const bool i0 = gi < C0;
        #pragma unroll
        for (int j = 0; j < 8; j++) {
            const int gj = gj0 + j;
            if (gi < N && gj < N && gi < gj && ((gj < C0) == i0)) {
                const float e = __expf(acc[i][j] * 10.0f);
                if (i0) s0 += e; else s1 += e;
            }
        }
    }

    // deterministic in-block reduction, write per-block partials
    red[tid] = s0; __syncthreads();
    for (int o = 128; o; o >>= 1) { if (tid < o) red[tid] += red[tid + o]; __syncthreads(); }
    if (tid == 0) g_part[outIdx] = red[0];
    __syncthreads();
    red[tid] = s1; __syncthreads();
    for (int o = 128; o; o >>= 1) { if (tid < o) red[tid] += red[tid + o]; __syncthreads(); }
    if (tid == 0) g_part[outIdx + 1] = red[0];
}

// ---------------------------------------------------------------------------
// Kernel 4: fixed-order final reduction + class normalization
// ---------------------------------------------------------------------------
__global__ void final_kernel(float* __restrict__ out, int nblocks, int N) {
    __shared__ float r0[256], r1[256];
    const int t = threadIdx.x;
    float s0 = 0.0f, s1 = 0.0f;
    for (int b = t; b < nblocks; b += 256) {
        s0 += g_part[2 * b];
        s1 += g_part[2 * b + 1];
    }
    r0[t] = s0; r1[t] = s1; __syncthreads();
    for (int o = 128; o; o >>= 1) {
        if (t < o) { r0[t] += r0[t + o]; r1[t] += r1[t + o]; }
        __syncthreads();
    }
    if (t == 0) {
        const int C0 = g_c0, C1 = N - C0;
        float res = 0.0f;
        if (C0 > 1) res += 2.0f * r0[0] / (float)(C0 - 1);   // x2: unordered -> ordered pairs
        if (C1 > 1) res += 2.0f * r1[0] / (float)(C1 - 1);
        out[0] = res;
    }
}

// ---------------------------------------------------------------------------
extern "C" void kernel_launch(void* const* d_in, const int* in_sizes, int n_in,
                              void* d_out, int out_size) {
    const float* emb   = (const float*)d_in[0];
    const int*   label = (const int*)d_in[1];
    const int N = in_sizes[1];                     // label element count
    const int T = (N + TILE - 1) / TILE;
    const int nb = T * (T + 1) / 2;

    group_kernel<<<1, 1024>>>(label, N);
    norm_kernel<<<(N + 7) / 8, 256>>>(emb, N);
    tile_kernel<<<nb, 256>>>(N, T);
    final_kernel<<<1, 256>>>((float*)d_out, nb, N);
}

// round 4
// speedup vs baseline: 1.4752x; 1.4752x over previous
#include <cuda_runtime.h>
#include <cuda_bf16.h>
#include <math.h>
#include <stdint.h>

#define MAXN   8192
#define TILE   128
#define MAXT   (MAXN / TILE)                       // 64
#define MAXNB  (MAXT * (MAXT + 1) / 2)             // 2080
#define RSTRIDE 272                                // 128 bf16 = 256B + 16B pad (conflict-free ldmatrix)
#define ARRB   (128 * RSTRIDE)                     // 34816 B per tile array

// ---------------- device scratch (allocation-free) ----------------
__device__ __nv_bfloat16 g_hi[MAXN * 128];         // hi bf16 of normalized rows (grouped)
__device__ __nv_bfloat16 g_lo[MAXN * 128];         // lo bf16 residual
__device__ int   g_src[MAXN];
__device__ int   g_c0;
__device__ float g_part[MAXNB * 2];

__device__ __forceinline__ uint32_t smem_u32(const void* p) {
    uint32_t a;
    asm("{ .reg .u64 t; cvta.to.shared.u64 t, %1; cvt.u32.u64 %0, t; }" : "=r"(a) : "l"(p));
    return a;
}
#define STS128(addr, r0, r1, r2, r3) \
    asm volatile("st.shared.v4.b32 [%0], {%1,%2,%3,%4};" :: "r"(addr), "r"(r0), "r"(r1), "r"(r2), "r"(r3) : "memory")

__device__ __forceinline__ void ldsm_x4(uint32_t* r, uint32_t addr) {
    asm volatile("ldmatrix.sync.aligned.m8n8.x4.shared.b16 {%0,%1,%2,%3}, [%4];"
                 : "=r"(r[0]), "=r"(r[1]), "=r"(r[2]), "=r"(r[3]) : "r"(addr));
}
__device__ __forceinline__ void ldsm_x2(uint32_t* r, uint32_t addr) {
    asm volatile("ldmatrix.sync.aligned.m8n8.x2.shared.b16 {%0,%1}, [%2];"
                 : "=r"(r[0]), "=r"(r[1]) : "r"(addr));
}
__device__ __forceinline__ void mma16816(float* d, const uint32_t* a, const uint32_t* b) {
    asm volatile("mma.sync.aligned.m16n8k16.row.col.f32.bf16.bf16.f32 "
                 "{%0,%1,%2,%3}, {%4,%5,%6,%7}, {%8,%9}, {%0,%1,%2,%3};"
                 : "+f"(d[0]), "+f"(d[1]), "+f"(d[2]), "+f"(d[3])
                 : "r"(a[0]), "r"(a[1]), "r"(a[2]), "r"(a[3]), "r"(b[0]), "r"(b[1]));
}

// ---------------------------------------------------------------------------
// Kernel 1: deterministic stable grouping permutation (single block scan)
// ---------------------------------------------------------------------------
__global__ void group_kernel(const int* __restrict__ label, int N) {
    __shared__ int sh[1024];
    const int t = threadIdx.x, NT = blockDim.x;
    const int chunk = (N + NT - 1) / NT;
    const int s = min(t * chunk, N), e = min(s + chunk, N);

    int c0 = 0;
    for (int i = s; i < e; i++) c0 += (label[i] == 0);
    sh[t] = c0;
    __syncthreads();
    for (int off = 1; off < NT; off <<= 1) {
        int v = (t >= off) ? sh[t - off] : 0;
        __syncthreads();
        sh[t] += v;
        __syncthreads();
    }
    const int incl = sh[t], C0 = sh[NT - 1];
    if (t == 0) g_c0 = C0;
    int p0 = incl - c0, p1 = s - p0;
    for (int i = s; i < e; i++) {
        if (label[i] == 0) g_src[p0++] = i;
        else               g_src[C0 + p1++] = i;
    }
}

// ---------------------------------------------------------------------------
// Kernel 2: normalize rows, split fp32 -> (hi, lo) bf16, gather into grouped order
// ---------------------------------------------------------------------------
__global__ void norm_kernel(const float* __restrict__ emb, int N) {
    const int r = blockIdx.x * 8 + (threadIdx.x >> 5);
    const int lane = threadIdx.x & 31;
    if (r >= N) return;
    const int src = g_src[r];
    float4 v = ((const float4*)(emb + (size_t)src * 128))[lane];
    float ss = v.x * v.x + v.y * v.y + v.z * v.z + v.w * v.w;
    #pragma unroll
    for (int o = 16; o; o >>= 1) ss += __shfl_xor_sync(0xffffffffu, ss, o);
    const float scale = 1.0f / fmaxf(sqrtf(ss), 1e-12f);
    float x[4] = {v.x * scale, v.y * scale, v.z * scale, v.w * scale};

    __nv_bfloat16 h[4], l[4];
    #pragma unroll
    for (int i = 0; i < 4; i++) {
        h[i] = __float2bfloat16(x[i]);
        l[i] = __float2bfloat16(x[i] - __bfloat162float(h[i]));
    }
    uint2 ph, pl;
    ph.x = (uint32_t)__bfloat16_as_ushort(h[0]) | ((uint32_t)__bfloat16_as_ushort(h[1]) << 16);
    ph.y = (uint32_t)__bfloat16_as_ushort(h[2]) | ((uint32_t)__bfloat16_as_ushort(h[3]) << 16);
    pl.x = (uint32_t)__bfloat16_as_ushort(l[0]) | ((uint32_t)__bfloat16_as_ushort(l[1]) << 16);
    pl.y = (uint32_t)__bfloat16_as_ushort(l[2]) | ((uint32_t)__bfloat16_as_ushort(l[3]) << 16);
    ((uint2*)(g_hi + (size_t)r * 128))[lane] = ph;
    ((uint2*)(g_lo + (size_t)r * 128))[lane] = pl;
}

// ---------------------------------------------------------------------------
// Kernel 3: HMMA bf16 split-GEMM tile kernel (128x128 tiles, triangular grid)
//   D = A_hi.B_hi^T + A_hi.B_lo^T + A_lo.B_hi^T  (fp32 reg accum) -> exp/mask
//   8 warps: 2(m) x 4(n) grid, 64x32 per warp, mma.sync.m16n8k16
// ---------------------------------------------------------------------------
__global__ __launch_bounds__(256, 1) void tile_mma_kernel(int N, int T) {
    // triangular decode: blockIdx.x -> (bi, bj), bj >= bi
    const int b = blockIdx.x;
    const float Tf = (float)T;
    int bi = (int)(Tf + 0.5f - sqrtf((Tf + 0.5f) * (Tf + 0.5f) - 2.0f * (float)b));
    while (bi > 0 && b < bi * T - bi * (bi - 1) / 2) bi--;
    while (b >= (bi + 1) * T - bi * (bi + 1) / 2) bi++;
    const int bj = bi + (b - (bi * T - bi * (bi - 1) / 2));
    const int rb = bi * TILE, cb = bj * TILE;
    const int C0 = g_c0;
    const int outIdx = blockIdx.x * 2;
    const int tid = threadIdx.x, wid = tid >> 5, lane = tid & 31;

    if (rb + TILE <= C0 && cb >= C0) {             // fully cross-class: no pairs
        if (tid == 0) { g_part[outIdx] = 0.0f; g_part[outIdx + 1] = 0.0f; }
        return;
    }

    __shared__ float red[256];
    extern __shared__ char dsm[];
    const uint32_t base = smem_u32(dsm);
    const uint32_t sAh = base, sAl = base + ARRB, sBh = base + 2 * ARRB, sBl = base + 3 * ARRB;
    const bool diag = (bi == bj);

    // load tiles: 128 rows x 128 bf16 each; padded rows (RSTRIDE bytes)
    for (int c = tid; c < 2048; c += 256) {
        const int row = c >> 4, col16 = c & 15;
        const uint32_t off = (uint32_t)row * RSTRIDE + (uint32_t)col16 * 16;
        const size_t ra = (size_t)(rb + row) * 128 + col16 * 8;
        uint4 vah = *(const uint4*)(g_hi + ra);
        uint4 val = *(const uint4*)(g_lo + ra);
        STS128(sAh + off, vah.x, vah.y, vah.z, vah.w);
        STS128(sAl + off, val.x, val.y, val.z, val.w);
        if (!diag) {
            const size_t rc = (size_t)(cb + row) * 128 + col16 * 8;
            uint4 vbh = *(const uint4*)(g_hi + rc);
            uint4 vbl = *(const uint4*)(g_lo + rc);
            STS128(sBh + off, vbh.x, vbh.y, vbh.z, vbh.w);
            STS128(sBl + off, vbl.x, vbl.y, vbl.z, vbl.w);
        }
    }
    __syncthreads();

    const uint32_t bH = diag ? sAh : sBh;
    const uint32_t bL = diag ? sAl : sBl;

    const int wm = wid & 1;                        // 0..1 : 64-row slab
    const int wn = wid >> 1;                       // 0..3 : 32-col slab

    float acc[4][4][4];
    #pragma unroll
    for (int mt = 0; mt < 4; mt++)
        #pragma unroll
        for (int nt = 0; nt < 4; nt++)
            #pragma unroll
            for (int q = 0; q < 4; q++) acc[mt][nt][q] = 0.0f;

    // per-lane ldmatrix address pieces
    const uint32_t aLaneOff = (uint32_t)(wm * 64 + (lane & 15)) * RSTRIDE + (uint32_t)(lane >> 4) * 16;
    const uint32_t bLaneOff = (uint32_t)(wn * 32 + (lane & 7)) * RSTRIDE + (uint32_t)((lane >> 3) & 1) * 16;

    const uint32_t aArr[3] = {sAh, sAh, sAl};
    const uint32_t bArr[3] = {bH,  bL,  bH };

    #pragma unroll
    for (int t = 0; t < 3; t++) {
        const uint32_t aBase = aArr[t] + aLaneOff;
        const uint32_t bBase = bArr[t] + bLaneOff;
        #pragma unroll
        for (int k = 0; k < 8; k++) {
            const uint32_t kB = (uint32_t)k * 32;  // 16 bf16 = 32 bytes
            uint32_t af[4][4], bf[4][2];
            #pragma unroll
            for (int mt = 0; mt < 4; mt++) ldsm_x4(af[mt], aBase + (uint32_t)mt * 16 * RSTRIDE + kB);
            #pragma unroll
            for (int nt = 0; nt < 4; nt++) ldsm_x2(bf[nt], bBase + (uint32_t)nt * 8 * RSTRIDE + kB);
            #pragma unroll
            for (int mt = 0; mt < 4; mt++)
                #pragma unroll
                for (int nt = 0; nt < 4; nt++)
                    mma16816(acc[mt][nt], af[mt], bf[nt]);
        }
    }

    // epilogue: exp + label mask + strict upper triangle (i < j)
    float s0 = 0.0f, s1 = 0.0f;
    const int rIn = lane >> 2, cIn = (lane & 3) * 2;
    #pragma unroll
    for (int mt = 0; mt < 4; mt++) {
        #pragma unroll
        for (int nt = 0; nt < 4; nt++) {
            const int gi_a = rb + wm * 64 + mt * 16 + rIn;
            const int gj_a = cb + wn * 32 + nt * 8 + cIn;
            #pragma unroll
            for (int q = 0; q < 4; q++) {
                const int gi = gi_a + (q >> 1) * 8;
                const int gj = gj_a + (q & 1);
                const bool i0 = gi < C0;
                if (gi < N && gj < N && gi < gj && ((gj < C0) == i0)) {
                    const float e = __expf(acc[mt][nt][q] * 10.0f);
                    if (i0) s0 += e; else s1 += e;
                }
            }
        }
    }

    // deterministic block reduction
    red[tid] = s0; __syncthreads();
    for (int o = 128; o; o >>= 1) { if (tid < o) red[tid] += red[tid + o]; __syncthreads(); }
    if (tid == 0) g_part[outIdx] = red[0];
    __syncthreads();
    red[tid] = s1; __syncthreads();
    for (int o = 128; o; o >>= 1) { if (tid < o) red[tid] += red[tid + o]; __syncthreads(); }
    if (tid == 0) g_part[outIdx + 1] = red[0];
}

// ---------------------------------------------------------------------------
// Kernel 4: fixed-order final reduction + class normalization
// ---------------------------------------------------------------------------
__global__ void final_kernel(float* __restrict__ out, int nblocks, int N) {
    __shared__ float r0[256], r1[256];
    const int t = threadIdx.x;
    float s0 = 0.0f, s1 = 0.0f;
    for (int b = t; b < nblocks; b += 256) {
        s0 += g_part[2 * b];
        s1 += g_part[2 * b + 1];
    }
    r0[t] = s0; r1[t] = s1; __syncthreads();
    for (int o = 128; o; o >>= 1) {
        if (t < o) { r0[t] += r0[t + o]; r1[t] += r1[t + o]; }
        __syncthreads();
    }
    if (t == 0) {
        const int C0 = g_c0, C1 = N - C0;
        float res = 0.0f;
        if (C0 > 1) res += 2.0f * r0[0] / (float)(C0 - 1);
        if (C1 > 1) res += 2.0f * r1[0] / (float)(C1 - 1);
        out[0] = res;
    }
}

// ---------------------------------------------------------------------------
extern "C" void kernel_launch(void* const* d_in, const int* in_sizes, int n_in,
                              void* d_out, int out_size) {
    const float* emb   = (const float*)d_in[0];
    const int*   label = (const int*)d_in[1];
    const int N = in_sizes[1];
    const int T = (N + TILE - 1) / TILE;
    const int nb = T * (T + 1) / 2;
    const int dyn = 4 * ARRB;                      // 139264 B

    cudaFuncSetAttribute(tile_mma_kernel, cudaFuncAttributeMaxDynamicSharedMemorySize, dyn);

    group_kernel<<<1, 1024>>>(label, N);
    norm_kernel<<<(N + 7) / 8, 256>>>(emb, N);
    tile_mma_kernel<<<nb, 256, dyn>>>(N, T);
    final_kernel<<<1, 256>>>((float*)d_out, nb, N);
}

// round 6
// speedup vs baseline: 1.6585x; 1.1242x over previous
#include <cuda_runtime.h>
#include <cuda_bf16.h>
#include <math.h>
#include <stdint.h>

#define MAXN    8192
#define TILE    128
#define RSTRIDE 272                                // 256B row + 16B pad (conflict-free ldmatrix)
#define ARRB    (128 * RSTRIDE)                    // 34816 B per tile array
#define GRID    148

// ---------------- device scratch (allocation-free) ----------------
__device__ __nv_bfloat16 g_hi[MAXN * 128];
__device__ __nv_bfloat16 g_lo[MAXN * 128];
__device__ int   g_src[MAXN];
__device__ int   g_c0;
__device__ float g_part[GRID * 2];

__device__ __forceinline__ uint32_t smem_u32(const void* p) {
    uint32_t a;
    asm("{ .reg .u64 t; cvta.to.shared.u64 t, %1; cvt.u32.u64 %0, t; }" : "=r"(a) : "l"(p));
    return a;
}
#define STS128(addr, r0, r1, r2, r3) \
    asm volatile("st.shared.v4.b32 [%0], {%1,%2,%3,%4};" :: "r"(addr), "r"(r0), "r"(r1), "r"(r2), "r"(r3) : "memory")

__device__ __forceinline__ void ldsm_x4(uint32_t* r, uint32_t addr) {
    asm volatile("ldmatrix.sync.aligned.m8n8.x4.shared.b16 {%0,%1,%2,%3}, [%4];"
                 : "=r"(r[0]), "=r"(r[1]), "=r"(r[2]), "=r"(r[3]) : "r"(addr));
}
__device__ __forceinline__ void ldsm_x2(uint32_t* r, uint32_t addr) {
    asm volatile("ldmatrix.sync.aligned.m8n8.x2.shared.b16 {%0,%1}, [%2];"
                 : "=r"(r[0]), "=r"(r[1]) : "r"(addr));
}
__device__ __forceinline__ void mma16816(float* d, const uint32_t* a, const uint32_t* b) {
    asm volatile("mma.sync.aligned.m16n8k16.row.col.f32.bf16.bf16.f32 "
                 "{%0,%1,%2,%3}, {%4,%5,%6,%7}, {%8,%9}, {%0,%1,%2,%3};"
                 : "+f"(d[0]), "+f"(d[1]), "+f"(d[2]), "+f"(d[3])
                 : "r"(a[0]), "r"(a[1]), "r"(a[2]), "r"(a[3]), "r"(b[0]), "r"(b[1]));
}
__device__ __forceinline__ void cp16(uint32_t dst, const void* src, bool v) {
    asm volatile("cp.async.cg.shared.global [%0], [%1], 16, %2;"
                 :: "r"(dst), "l"(src), "r"(v ? 16 : 0) : "memory");
}
#define CP_COMMIT()  asm volatile("cp.async.commit_group;" ::: "memory")
#define CP_WAIT1()   asm volatile("cp.async.wait_group 1;" ::: "memory")

// ---------------------------------------------------------------------------
// Kernel 1: deterministic stable grouping permutation (single block scan)
// ---------------------------------------------------------------------------
__global__ void group_kernel(const int* __restrict__ label, int N) {
    __shared__ int sh[1024];
    const int t = threadIdx.x, NT = blockDim.x;
    const int chunk = (N + NT - 1) / NT;
    const int s = min(t * chunk, N), e = min(s + chunk, N);
    int c0 = 0;
    for (int i = s; i < e; i++) c0 += (label[i] == 0);
    sh[t] = c0;
    __syncthreads();
    for (int off = 1; off < NT; off <<= 1) {
        int v = (t >= off) ? sh[t - off] : 0;
        __syncthreads();
        sh[t] += v;
        __syncthreads();
    }
    const int incl = sh[t], C0 = sh[NT - 1];
    if (t == 0) g_c0 = C0;
    int p0 = incl - c0, p1 = s - p0;
    for (int i = s; i < e; i++) {
        if (label[i] == 0) g_src[p0++] = i;
        else               g_src[C0 + p1++] = i;
    }
}

// ---------------------------------------------------------------------------
// Kernel 2: normalize rows, split fp32 -> (hi, lo) bf16, gather grouped
// ---------------------------------------------------------------------------
__global__ void norm_kernel(const float* __restrict__ emb, int N) {
    const int r = blockIdx.x * 8 + (threadIdx.x >> 5);
    const int lane = threadIdx.x & 31;
    if (r >= N) return;
    const int src = g_src[r];
    float4 v = ((const float4*)(emb + (size_t)src * 128))[lane];
    float ss = v.x * v.x + v.y * v.y + v.z * v.z + v.w * v.w;
    #pragma unroll
    for (int o = 16; o; o >>= 1) ss += __shfl_xor_sync(0xffffffffu, ss, o);
    const float scale = 1.0f / fmaxf(sqrtf(ss), 1e-12f);
    float x[4] = {v.x * scale, v.y * scale, v.z * scale, v.w * scale};
    __nv_bfloat16 h[4], l[4];
    #pragma unroll
    for (int i = 0; i < 4; i++) {
        h[i] = __float2bfloat16(x[i]);
        l[i] = __float2bfloat16(x[i] - __bfloat162float(h[i]));
    }
    uint2 ph, pl;
    ph.x = (uint32_t)__bfloat16_as_ushort(h[0]) | ((uint32_t)__bfloat16_as_ushort(h[1]) << 16);
    ph.y = (uint32_t)__bfloat16_as_ushort(h[2]) | ((uint32_t)__bfloat16_as_ushort(h[3]) << 16);
    pl.x = (uint32_t)__bfloat16_as_ushort(l[0]) | ((uint32_t)__bfloat16_as_ushort(l[1]) << 16);
    pl.y = (uint32_t)__bfloat16_as_ushort(l[2]) | ((uint32_t)__bfloat16_as_ushort(l[3]) << 16);
    ((uint2*)(g_hi + (size_t)r * 128))[lane] = ph;
    ((uint2*)(g_lo + (size_t)r * 128))[lane] = pl;
}

// ---------------------------------------------------------------------------
// Kernel 3: persistent HMMA split-GEMM. A-resident per tile row, B double-
// buffered via cp.async. 8 warps (2m x 4n), 64x32/warp, mma.m16n8k16 bf16.
// ---------------------------------------------------------------------------
__device__ __forceinline__ void issue_B(uint32_t dHi, uint32_t dLo, int bj, int N, int tid) {
    #pragma unroll
    for (int it = 0; it < 8; it++) {
        const int c = tid + it * 256;
        const int row = c >> 4, col16 = c & 15;
        const uint32_t off = (uint32_t)row * RSTRIDE + (uint32_t)col16 * 16;
        const int gr = bj * TILE + row;
        const bool v = gr < N;
        const size_t g = (size_t)min(gr, N - 1) * 128 + col16 * 8;
        cp16(dHi + off, g_hi + g, v);
        cp16(dLo + off, g_lo + g, v);
    }
}

__global__ __launch_bounds__(256, 1) void tile_pers_kernel(int N, int T) {
    const int tid = threadIdx.x, wid = tid >> 5, lane = tid & 31;
    const int C0 = g_c0;
    const int C1s = (C0 + TILE - 1) >> 7;          // first fully-class1 tile col
    const int F0  = C0 >> 7;                       // rows fully class0
    const int F1  = T - C1s;
    const int nvalid = T * (T + 1) / 2 - F0 * F1;
    const int G = gridDim.x;
    const int q = nvalid / G, rmd = nvalid % G;
    const int start = blockIdx.x * q + min(blockIdx.x, rmd);
    const int end   = start + q + (blockIdx.x < rmd ? 1 : 0);

    extern __shared__ char dsm[];
    const uint32_t base = smem_u32(dsm);
    const uint32_t sAh = base, sAl = base + ARRB;
    const uint32_t sBh0 = base + 2 * ARRB, sBl0 = base + 3 * ARRB;
    const uint32_t sBh1 = base + 4 * ARRB, sBl1 = base + 5 * ARRB;
    float* red = (float*)(dsm + 6 * ARRB);

    const int wm = wid & 1, wn = wid >> 1;
    const uint32_t aLaneOff = (uint32_t)(wm * 64 + (lane & 15)) * RSTRIDE + (uint32_t)(lane >> 4) * 16;
    const uint32_t bLaneOff = (uint32_t)(wn * 32 + (lane & 7)) * RSTRIDE + (uint32_t)((lane >> 3) & 1) * 16;
    const int rIn = lane >> 2, cIn = (lane & 3) * 2;

    float s0 = 0.0f, s1 = 0.0f;

    if (start < end) {
        // map start -> (bi, bj)
        int bi = 0, bj = 0, k = 0;
        for (;;) {
            const int rowEnd = (bi < F0) ? C1s : T;
            const int cnt = rowEnd - bi;
            if (k + cnt > start) { bj = bi + (start - k); break; }
            k += cnt; bi++;
        }
        int pbi = bi, pbj = bj;                    // prefetch cursor
        // prologue: prefetch first tile's B (empty group if diagonal)
        if (pbi != pbj) issue_B(sBh0, sBl0, pbj, N, tid);
        CP_COMMIT();

        int curA = -1;
        for (int idx = start; idx < end; idx++) {
            const int buf = (idx - start) & 1;
            const uint32_t cBh = buf ? sBh1 : sBh0, cBl = buf ? sBl1 : sBl0;
            const uint32_t nBh = buf ? sBh0 : sBh1, nBl = buf ? sBl0 : sBl1;
            const bool diag = (bi == bj);

            // prefetch next tile's B into the other buffer
            if (idx + 1 < end) {
                pbj++;
                const int rowEnd = (pbi < F0) ? C1s : T;
                if (pbj >= rowEnd) { pbi++; pbj = pbi; }
                if (pbi != pbj) issue_B(nBh, nBl, pbj, N, tid);
            }
            CP_COMMIT();
            CP_WAIT1();
            __syncthreads();

            if (bi != curA) {                      // reload A (rare: row change)
                #pragma unroll
                for (int it = 0; it < 8; it++) {
                    const int c = tid + it * 256;
                    const int row = c >> 4, col16 = c & 15;
                    const uint32_t off = (uint32_t)row * RSTRIDE + (uint32_t)col16 * 16;
                    const size_t g = (size_t)min(bi * TILE + row, N - 1) * 128 + col16 * 8;
                    uint4 h = *(const uint4*)(g_hi + g);
                    uint4 l = *(const uint4*)(g_lo + g);
                    STS128(sAh + off, h.x, h.y, h.z, h.w);
                    STS128(sAl + off, l.x, l.y, l.z, l.w);
                }
                curA = bi;
                __syncthreads();
            }

            const uint32_t bH = diag ? sAh : cBh;
            const uint32_t bL = diag ? sAl : cBl;
            const int rb = bi * TILE, cb = bj * TILE;

            float acc[4][4][4];
            #pragma unroll
            for (int mt = 0; mt < 4; mt++)
                #pragma unroll
                for (int nt = 0; nt < 4; nt++)
                    #pragma unroll
                    for (int p = 0; p < 4; p++) acc[mt][nt][p] = 0.0f;

            const uint32_t aArr[3] = {sAh, sAh, sAl};
            const uint32_t bArr[3] = {bH,  bL,  bH };
            #pragma unroll
            for (int t = 0; t < 3; t++) {
                const uint32_t aBase = aArr[t] + aLaneOff;
                const uint32_t bBase = bArr[t] + bLaneOff;
                #pragma unroll
                for (int kk = 0; kk < 8; kk++) {
                    const uint32_t kB = (uint32_t)kk * 32;
                    uint32_t af[4][4], bf[4][2];
                    #pragma unroll
                    for (int mt = 0; mt < 4; mt++) ldsm_x4(af[mt], aBase + (uint32_t)mt * 16 * RSTRIDE + kB);
                    #pragma unroll
                    for (int nt = 0; nt < 4; nt++) ldsm_x2(bf[nt], bBase + (uint32_t)nt * 8 * RSTRIDE + kB);
                    #pragma unroll
                    for (int mt = 0; mt < 4; mt++)
                        #pragma unroll
                        for (int nt = 0; nt < 4; nt++)
                            mma16816(acc[mt][nt], af[mt], bf[nt]);
                }
            }

            // epilogue: exp + mask, accumulate into running registers
            #pragma unroll
            for (int mt = 0; mt < 4; mt++) {
                #pragma unroll
                for (int nt = 0; nt < 4; nt++) {
                    const int gi0 = rb + wm * 64 + mt * 16;
                    const int gj0 = cb + wn * 32 + nt * 8;
                    if (gi0 >= gj0 + 7) continue;                          // all gi >= gj
                    if (gi0 + 15 < C0 && gj0 >= C0) continue;              // fully cross-class
                    if (gi0 >= C0 && gj0 + 7 < C0) continue;               // (defensive)
                    #pragma unroll
                    for (int p = 0; p < 4; p++) {
                        const int gi = gi0 + rIn + (p >> 1) * 8;
                        const int gj = gj0 + cIn + (p & 1);
                        const bool i0 = gi < C0;
                        if (gi < N && gj < N && gi < gj && ((gj < C0) == i0)) {
                            const float e = __expf(acc[mt][nt][p] * 10.0f);
                            if (i0) s0 += e; else s1 += e;
                        }
                    }
                }
            }
            __syncthreads();                       // protect buffers before next overwrite

            // advance current cursor
            bj++;
            const int rowEnd = (bi < F0) ? C1s : T;
            if (bj >= rowEnd) { bi++; bj = bi; }
        }
    }

    // single deterministic block reduction at the end
    red[tid] = s0; __syncthreads();
    for (int o = 128; o; o >>= 1) { if (tid < o) red[tid] += red[tid + o]; __syncthreads(); }
    if (tid == 0) g_part[blockIdx.x * 2] = red[0];
    __syncthreads();
    red[tid] = s1; __syncthreads();
    for (int o = 128; o; o >>= 1) { if (tid < o) red[tid] += red[tid + o]; __syncthreads(); }
    if (tid == 0) g_part[blockIdx.x * 2 + 1] = red[0];
}

// ---------------------------------------------------------------------------
// Kernel 4: fixed-order final reduction + class normalization
// ---------------------------------------------------------------------------
__global__ void final_kernel(float* __restrict__ out, int nblocks, int N) {
    __shared__ float r0[256], r1[256];
    const int t = threadIdx.x;
    float s0 = 0.0f, s1 = 0.0f;
    for (int b = t; b < nblocks; b += 256) {
        s0 += g_part[2 * b];
        s1 += g_part[2 * b + 1];
    }
    r0[t] = s0; r1[t] = s1; __syncthreads();
    for (int o = 128; o; o >>= 1) {
        if (t < o) { r0[t] += r0[t + o]; r1[t] += r1[t + o]; }
        __syncthreads();
    }
    if (t == 0) {
        const int C0 = g_c0, C1 = N - C0;
        float res = 0.0f;
        if (C0 > 1) res += 2.0f * r0[0] / (float)(C0 - 1);
        if (C1 > 1) res += 2.0f * r1[0] / (float)(C1 - 1);
        out[0] = res;
    }
}

// ---------------------------------------------------------------------------
extern "C" void kernel_launch(void* const* d_in, const int* in_sizes, int n_in,
                              void* d_out, int out_size) {
    const float* emb   = (const float*)d_in[0];
    const int*   label = (const int*)d_in[1];
    const int N = in_sizes[1];
    const int T = (N + TILE - 1) / TILE;
    const int dyn = 6 * ARRB + 1024;               // 209920 B

    cudaFuncSetAttribute(tile_pers_kernel, cudaFuncAttributeMaxDynamicSharedMemorySize, dyn);

    group_kernel<<<1, 1024>>>(label, N);
    norm_kernel<<<(N + 7) / 8, 256>>>(emb, N);
    tile_pers_kernel<<<GRID, 256, dyn>>>(N, T);
    final_kernel<<<1, 256>>>((float*)d_out, GRID, N);
}

// round 7
// speedup vs baseline: 1.7349x; 1.0460x over previous
#include <cuda_runtime.h>
#include <cuda_bf16.h>
#include <math.h>
#include <stdint.h>

#define MAXN    8192
#define TILE    128
#define RSTRIDE 272                                // 256B row + 16B pad (conflict-free ldmatrix)
#define ARRB    (128 * RSTRIDE)                    // 34816 B per tile array
#define GRID    148

// ---------------- device scratch (allocation-free) ----------------
__device__ __nv_bfloat16 g_hi[MAXN * 128];
__device__ __nv_bfloat16 g_lo[MAXN * 128];
__device__ int   g_src[MAXN];
__device__ int   g_c0;
__device__ float g_part[GRID * 2];
__device__ int   g_done;                           // last-block ticket (reset each run)

__device__ __forceinline__ uint32_t smem_u32(const void* p) {
    uint32_t a;
    asm("{ .reg .u64 t; cvta.to.shared.u64 t, %1; cvt.u32.u64 %0, t; }" : "=r"(a) : "l"(p));
    return a;
}
__device__ __forceinline__ void ldsm_x4(uint32_t* r, uint32_t addr) {
    asm volatile("ldmatrix.sync.aligned.m8n8.x4.shared.b16 {%0,%1,%2,%3}, [%4];"
                 : "=r"(r[0]), "=r"(r[1]), "=r"(r[2]), "=r"(r[3]) : "r"(addr));
}
__device__ __forceinline__ void ldsm_x2(uint32_t* r, uint32_t addr) {
    asm volatile("ldmatrix.sync.aligned.m8n8.x2.shared.b16 {%0,%1}, [%2];"
                 : "=r"(r[0]), "=r"(r[1]) : "r"(addr));
}
__device__ __forceinline__ void mma16816(float* d, const uint32_t* a, const uint32_t* b) {
    asm volatile("mma.sync.aligned.m16n8k16.row.col.f32.bf16.bf16.f32 "
                 "{%0,%1,%2,%3}, {%4,%5,%6,%7}, {%8,%9}, {%0,%1,%2,%3};"
                 : "+f"(d[0]), "+f"(d[1]), "+f"(d[2]), "+f"(d[3])
                 : "r"(a[0]), "r"(a[1]), "r"(a[2]), "r"(a[3]), "r"(b[0]), "r"(b[1]));
}
__device__ __forceinline__ void cp16(uint32_t dst, const void* src, bool v) {
    asm volatile("cp.async.cg.shared.global [%0], [%1], 16, %2;"
                 :: "r"(dst), "l"(src), "r"(v ? 16 : 0) : "memory");
}
#define CP_COMMIT()  asm volatile("cp.async.commit_group;" ::: "memory")
#define CP_WAIT1()   asm volatile("cp.async.wait_group 1;" ::: "memory")
#define CP_WAIT0()   asm volatile("cp.async.wait_group 0;" ::: "memory")

// ---------------------------------------------------------------------------
// Kernel 1: stable grouping permutation — hierarchical warp-shuffle scan
// ---------------------------------------------------------------------------
__global__ void group_kernel(const int* __restrict__ label, int N) {
    __shared__ int wsum[32];
    const int t = threadIdx.x, NT = blockDim.x;    // 1024
    const int wid = t >> 5, lane = t & 31;
    const int chunk = (N + NT - 1) / NT;
    const int s = min(t * chunk, N), e = min(s + chunk, N);

    int c0 = 0;
    for (int i = s; i < e; i++) c0 += (label[i] == 0);

    // warp inclusive scan
    int incl = c0;
    #pragma unroll
    for (int o = 1; o < 32; o <<= 1) {
        int v = __shfl_up_sync(0xffffffffu, incl, o);
        if (lane >= o) incl += v;
    }
    if (lane == 31) wsum[wid] = incl;
    __syncthreads();
    if (wid == 0) {
        int v = wsum[lane];
        #pragma unroll
        for (int o = 1; o < 32; o <<= 1) {
            int u = __shfl_up_sync(0xffffffffu, v, o);
            if (lane >= o) v += u;
        }
        wsum[lane] = v;
    }
    __syncthreads();
    const int C0 = wsum[31];
    incl += (wid > 0) ? wsum[wid - 1] : 0;         // block-wide inclusive
    if (t == 0) g_c0 = C0;

    int p0 = incl - c0, p1 = s - p0;
    for (int i = s; i < e; i++) {
        if (label[i] == 0) g_src[p0++] = i;
        else               g_src[C0 + p1++] = i;
    }
}

// ---------------------------------------------------------------------------
// Kernel 2: normalize rows, split fp32 -> (hi, lo) bf16, gather grouped
// ---------------------------------------------------------------------------
__global__ void norm_kernel(const float* __restrict__ emb, int N) {
    const int r = blockIdx.x * 8 + (threadIdx.x >> 5);
    const int lane = threadIdx.x & 31;
    if (r >= N) return;
    const int src = g_src[r];
    float4 v = ((const float4*)(emb + (size_t)src * 128))[lane];
    float ss = v.x * v.x + v.y * v.y + v.z * v.z + v.w * v.w;
    #pragma unroll
    for (int o = 16; o; o >>= 1) ss += __shfl_xor_sync(0xffffffffu, ss, o);
    const float scale = 1.0f / fmaxf(sqrtf(ss), 1e-12f);
    float x[4] = {v.x * scale, v.y * scale, v.z * scale, v.w * scale};
    __nv_bfloat16 h[4], l[4];
    #pragma unroll
    for (int i = 0; i < 4; i++) {
        h[i] = __float2bfloat16(x[i]);
        l[i] = __float2bfloat16(x[i] - __bfloat162float(h[i]));
    }
    uint2 ph, pl;
    ph.x = (uint32_t)__bfloat16_as_ushort(h[0]) | ((uint32_t)__bfloat16_as_ushort(h[1]) << 16);
    ph.y = (uint32_t)__bfloat16_as_ushort(h[2]) | ((uint32_t)__bfloat16_as_ushort(h[3]) << 16);
    pl.x = (uint32_t)__bfloat16_as_ushort(l[0]) | ((uint32_t)__bfloat16_as_ushort(l[1]) << 16);
    pl.y = (uint32_t)__bfloat16_as_ushort(l[2]) | ((uint32_t)__bfloat16_as_ushort(l[3]) << 16);
    ((uint2*)(g_hi + (size_t)r * 128))[lane] = ph;
    ((uint2*)(g_lo + (size_t)r * 128))[lane] = pl;
}

// ---------------------------------------------------------------------------
// Kernel 3: persistent HMMA split-GEMM + last-block final reduction
// ---------------------------------------------------------------------------
__device__ __forceinline__ void issue_tile(uint32_t dHi, uint32_t dLo, int b0, int N, int tid) {
    #pragma unroll
    for (int it = 0; it < 8; it++) {
        const int c = tid + it * 256;
        const int row = c >> 4, col16 = c & 15;
        const uint32_t off = (uint32_t)row * RSTRIDE + (uint32_t)col16 * 16;
        const int gr = b0 * TILE + row;
        const bool v = gr < N;
        const size_t g = (size_t)min(gr, N - 1) * 128 + col16 * 8;
        cp16(dHi + off, g_hi + g, v);
        cp16(dLo + off, g_lo + g, v);
    }
}

__global__ __launch_bounds__(256, 1) void tile_pers_kernel(float* __restrict__ out, int N, int T) {
    const int tid = threadIdx.x, wid = tid >> 5, lane = tid & 31;
    const int C0 = g_c0;
    const int C1s = (C0 + TILE - 1) >> 7;
    const int F0  = C0 >> 7;
    const int F1  = T - C1s;
    const int nvalid = T * (T + 1) / 2 - F0 * F1;
    const int G = gridDim.x;
    const int q = nvalid / G, rmd = nvalid % G;
    const int start = blockIdx.x * q + min(blockIdx.x, rmd);
    const int end   = start + q + (blockIdx.x < rmd ? 1 : 0);

    extern __shared__ char dsm[];
    const uint32_t base = smem_u32(dsm);
    const uint32_t sAh = base, sAl = base + ARRB;
    const uint32_t sBh0 = base + 2 * ARRB, sBl0 = base + 3 * ARRB;
    const uint32_t sBh1 = base + 4 * ARRB, sBl1 = base + 5 * ARRB;
    float* red = (float*)(dsm + 6 * ARRB);

    const int wm = wid & 1, wn = wid >> 1;
    const uint32_t aLaneOff = (uint32_t)(wm * 64 + (lane & 15)) * RSTRIDE + (uint32_t)(lane >> 4) * 16;
    const uint32_t bLaneOff = (uint32_t)(wn * 32 + (lane & 7)) * RSTRIDE + (uint32_t)((lane >> 3) & 1) * 16;
    const int rIn = lane >> 2, cIn = (lane & 3) * 2;

    float s0 = 0.0f, s1 = 0.0f;

    if (start < end) {
        int bi = 0, bj = 0, k = 0;
        for (;;) {
            const int rowEnd = (bi < F0) ? C1s : T;
            const int cnt = rowEnd - bi;
            if (k + cnt > start) { bj = bi + (start - k); break; }
            k += cnt; bi++;
        }
        int pbi = bi, pbj = bj;
        if (pbi != pbj) issue_tile(sBh0, sBl0, pbj, N, tid);
        CP_COMMIT();

        int curA = -1;
        for (int idx = start; idx < end; idx++) {
            const int buf = (idx - start) & 1;
            const uint32_t cBh = buf ? sBh1 : sBh0, cBl = buf ? sBl1 : sBl0;
            const uint32_t nBh = buf ? sBh0 : sBh1, nBl = buf ? sBl0 : sBl1;
            const bool diag = (bi == bj);

            if (idx + 1 < end) {
                pbj++;
                const int rowEnd = (pbi < F0) ? C1s : T;
                if (pbj >= rowEnd) { pbi++; pbj = pbi; }
                if (pbi != pbj) issue_tile(nBh, nBl, pbj, N, tid);
            }
            CP_COMMIT();
            CP_WAIT1();
            __syncthreads();

            if (bi != curA) {                      // rare: A row change (cp.async, full drain)
                issue_tile(sAh, sAl, bi, N, tid);
                CP_COMMIT();
                CP_WAIT0();
                curA = bi;
                __syncthreads();
            }

            const uint32_t bH = diag ? sAh : cBh;
            const uint32_t bL = diag ? sAl : cBl;
            const int rb = bi * TILE, cb = bj * TILE;

            // warp-level skips: entire warp region lower-triangle (diag tiles) or cross-class
            const int wr0 = rb + wm * 64, wc0 = cb + wn * 32;
            const bool skipWarp = (wr0 > wc0 + 31) || (wr0 + 63 < C0 && wc0 >= C0);

            if (!skipWarp) {
                float acc[4][4][4];
                #pragma unroll
                for (int mt = 0; mt < 4; mt++)
                    #pragma unroll
                    for (int nt = 0; nt < 4; nt++)
                        #pragma unroll
                        for (int p = 0; p < 4; p++) acc[mt][nt][p] = 0.0f;

                // combined-fragment mainloop: load Ah/Al/Bh/Bl once per k, 48 MMAs
                #pragma unroll
                for (int kk = 0; kk < 8; kk++) {
                    const uint32_t kB = (uint32_t)kk * 32;
                    uint32_t ah[4][4], al[4][4], bh[4][2], bl[4][2];
                    #pragma unroll
                    for (int mt = 0; mt < 4; mt++) {
                        const uint32_t ao = aLaneOff + (uint32_t)mt * 16 * RSTRIDE + kB;
                        ldsm_x4(ah[mt], sAh + ao);
                        ldsm_x4(al[mt], sAl + ao);
                    }
                    #pragma unroll
                    for (int nt = 0; nt < 4; nt++) {
                        const uint32_t bo = bLaneOff + (uint32_t)nt * 8 * RSTRIDE + kB;
                        ldsm_x2(bh[nt], bH + bo);
                        ldsm_x2(bl[nt], bL + bo);
                    }
                    #pragma unroll
                    for (int mt = 0; mt < 4; mt++)
                        #pragma unroll
                        for (int nt = 0; nt < 4; nt++) {
                            mma16816(acc[mt][nt], ah[mt], bh[nt]);
                            mma16816(acc[mt][nt], ah[mt], bl[nt]);
                            mma16816(acc[mt][nt], al[mt], bh[nt]);
                        }
                }

                // epilogue: exp + mask, accumulate into running registers
                #pragma unroll
                for (int mt = 0; mt < 4; mt++) {
                    #pragma unroll
                    for (int nt = 0; nt < 4; nt++) {
                        const int gi0 = wr0 + mt * 16;
                        const int gj0 = wc0 + nt * 8;
                        if (gi0 >= gj0 + 7) continue;
                        if (gi0 + 15 < C0 && gj0 >= C0) continue;
                        if (gi0 >= C0 && gj0 + 7 < C0) continue;
                        #pragma unroll
                        for (int p = 0; p < 4; p++) {
                            const int gi = gi0 + rIn + (p >> 1) * 8;
                            const int gj = gj0 + cIn + (p & 1);
                            const bool i0 = gi < C0;
                            if (gi < N && gj < N && gi < gj && ((gj < C0) == i0)) {
                                const float e = __expf(acc[mt][nt][p] * 10.0f);
                                if (i0) s0 += e; else s1 += e;
                            }
                        }
                    }
                }
            }
            __syncthreads();                       // protect buffers before next overwrite

            bj++;
            const int rowEnd = (bi < F0) ? C1s : T;
            if (bj >= rowEnd) { bi++; bj = bi; }
        }
    }

    // per-block deterministic reduction
    red[tid] = s0; __syncthreads();
    for (int o = 128; o; o >>= 1) { if (tid < o) red[tid] += red[tid + o]; __syncthreads(); }
    if (tid == 0) g_part[blockIdx.x * 2] = red[0];
    __syncthreads();
    red[tid] = s1; __syncthreads();
    for (int o = 128; o; o >>= 1) { if (tid < o) red[tid] += red[tid + o]; __syncthreads(); }
    if (tid == 0) g_part[blockIdx.x * 2 + 1] = red[0];

    // last-block final reduction (fixed order -> deterministic)
    __shared__ int s_ticket;
    __threadfence();
    if (tid == 0) s_ticket = atomicAdd(&g_done, 1);
    __syncthreads();
    if (s_ticket == G - 1) {
        __threadfence();
        float t0 = 0.0f, t1 = 0.0f;
        for (int b = tid; b < G; b += 256) { t0 += g_part[2 * b]; t1 += g_part[2 * b + 1]; }
        red[tid] = t0; __syncthreads();
        for (int o = 128; o; o >>= 1) { if (tid < o) red[tid] += red[tid + o]; __syncthreads(); }
        t0 = red[0]; __syncthreads();
        red[tid] = t1; __syncthreads();
        for (int o = 128; o; o >>= 1) { if (tid < o) red[tid] += red[tid + o]; __syncthreads(); }
        if (tid == 0) {
            const int c0n = C0, c1n = N - C0;
            float res = 0.0f;
            if (c0n > 1) res += 2.0f * t0 / (float)(c0n - 1);
            if (c1n > 1) res += 2.0f * red[0] / (float)(c1n - 1);
            out[0] = res;
            g_done = 0;                            // reset for next graph replay
        }
    }
}

// ---------------------------------------------------------------------------
extern "C" void kernel_launch(void* const* d_in, const int* in_sizes, int n_in,
                              void* d_out, int out_size) {
    const float* emb   = (const float*)d_in[0];
    const int*   label = (const int*)d_in[1];
    const int N = in_sizes[1];
    const int T = (N + TILE - 1) / TILE;
    const int dyn = 6 * ARRB + 1024;               // 209920 B

    cudaFuncSetAttribute(tile_pers_kernel, cudaFuncAttributeMaxDynamicSharedMemorySize, dyn);

    group_kernel<<<1, 1024>>>(label, N);
    norm_kernel<<<(N + 7) / 8, 256>>>(emb, N);
    tile_pers_kernel<<<GRID, 256, dyn>>>((float*)d_out, N, T);
}